// round 16
// baseline (speedup 1.0000x reference)
#include <cuda_runtime.h>
#include <cuda_bf16.h>
#include <mma.h>
#include <cstdint>

using namespace nvcuda;

// Problem dims
#define NB    8
#define NMAT  256
#define N3    64
#define NF    33
#define NPLANE (NMAT * NMAT)       // 65536
#define NTUBES (NB * NPLANE)       // 524288
#define NFP    (NB * NF)           // 264
#define PLSZ   ((size_t)NFP * NPLANE)

// Operand arrays: [6][plane][256][256] bf16. Order: rh, rl, ih, il, sh, sl
__device__ static __nv_bfloat16 g_A[6][PLSZ];
__device__ static __nv_bfloat16 g_B[6][PLSZ];
__device__ static float g_Cre[PLSZ];
__device__ static float g_Cim[PLSZ];

// ---------------------------------------------------------------------------
// Compile-time twiddles
// ---------------------------------------------------------------------------
__device__ constexpr float TW32R[16] = {
    1.0f, 0.980785280403230449f, 0.923879532511286756f, 0.831469612302545237f,
    0.707106781186547524f, 0.555570233019602225f, 0.382683432365089772f,
    0.195090322016128268f, 0.0f, -0.195090322016128268f, -0.382683432365089772f,
    -0.555570233019602225f, -0.707106781186547524f, -0.831469612302545237f,
    -0.923879532511286756f, -0.980785280403230449f };
__device__ constexpr float TW32I[16] = {
    0.0f, 0.195090322016128268f, 0.382683432365089772f, 0.555570233019602225f,
    0.707106781186547524f, 0.831469612302545237f, 0.923879532511286756f,
    0.980785280403230449f, 1.0f, 0.980785280403230449f, 0.923879532511286756f,
    0.831469612302545237f, 0.707106781186547524f, 0.555570233019602225f,
    0.382683432365089772f, 0.195090322016128268f };
__device__ constexpr float W64R[33] = {
    1.0f, 0.995184726672196886f, 0.980785280403230449f, 0.956940335732208865f,
    0.923879532511286756f, 0.881921264348355030f, 0.831469612302545237f,
    0.773010453362736961f, 0.707106781186547524f, 0.634393284163645498f,
    0.555570233019602225f, 0.471396736825997649f, 0.382683432365089772f,
    0.290284677254462368f, 0.195090322016128268f, 0.098017140329560602f,
    0.0f, -0.098017140329560602f, -0.195090322016128268f, -0.290284677254462368f,
    -0.382683432365089772f, -0.471396736825997649f, -0.555570233019602225f,
    -0.634393284163645498f, -0.707106781186547524f, -0.773010453362736961f,
    -0.831469612302545237f, -0.881921264348355030f, -0.923879532511286756f,
    -0.956940335732208865f, -0.980785280403230449f, -0.995184726672196886f, -1.0f };
__device__ constexpr float W64I[33] = {
    0.0f, 0.098017140329560602f, 0.195090322016128268f, 0.290284677254462368f,
    0.382683432365089772f, 0.471396736825997649f, 0.555570233019602225f,
    0.634393284163645498f, 0.707106781186547524f, 0.773010453362736961f,
    0.831469612302545237f, 0.881921264348355030f, 0.923879532511286756f,
    0.956940335732208865f, 0.980785280403230449f, 0.995184726672196886f,
    1.0f, 0.995184726672196886f, 0.980785280403230449f, 0.956940335732208865f,
    0.923879532511286756f, 0.881921264348355030f, 0.831469612302545237f,
    0.773010453362736961f, 0.707106781186547524f, 0.634393284163645498f,
    0.555570233019602225f, 0.471396736825997649f, 0.382683432365089772f,
    0.290284677254462368f, 0.195090322016128268f, 0.098017140329560602f, 0.0f };
__device__ constexpr int BR5[32] = {
    0,16,8,24,4,20,12,28,2,18,10,26,6,22,14,30,
    1,17,9,25,5,21,13,29,3,19,11,27,7,23,15,31 };

template<int M, int SIGN>
static __device__ __forceinline__ void fft32_stage(float* zr, float* zi) {
    constexpr int H = M / 2;
#pragma unroll
    for (int g = 0; g < 32; g += M)
#pragma unroll
        for (int j = 0; j < H; ++j) {
            const float wr = TW32R[j * (32 / M)];
            const float wi = SIGN * TW32I[j * (32 / M)];
            const int i0 = g + j, i1 = g + j + H;
            const float ar = zr[i0], ai = zi[i0];
            const float br_ = zr[i1], bi = zi[i1];
            zr[i0] = ar + br_;  zi[i0] = ai + bi;
            const float dr = ar - br_, di = ai - bi;
            zr[i1] = dr * wr - di * wi;
            zi[i1] = dr * wi + di * wr;
        }
}
template<int SIGN>
static __device__ __forceinline__ void fft32(float* zr, float* zi) {
    fft32_stage<32, SIGN>(zr, zi);
    fft32_stage<16, SIGN>(zr, zi);
    fft32_stage<8,  SIGN>(zr, zi);
    fft32_stage<4,  SIGN>(zr, zi);
    fft32_stage<2,  SIGN>(zr, zi);
}

// ===========================================================================
// Forward rfft64 (k=0..32); writes 6 planar bf16 operand arrays (Gauss form):
//   rh/rl = split(re), ih/il = split(im), sh/sl = split(re+im)
// A and B use identical [p][i*256+j] addressing.
// ===========================================================================
__global__ __launch_bounds__(128) void fft_fwd_kernel(const float* __restrict__ x, int sel)
{
    __shared__ float sx[128][N3 + 1];
    const int tid = threadIdx.x;

    const float* src = x + (size_t)blockIdx.x * 128 * N3;
    for (int i = tid; i < 128 * N3; i += 128)
        sx[i >> 6][i & 63] = src[i];
    __syncthreads();

    float zr[32], zi[32];
#pragma unroll
    for (int n = 0; n < 32; ++n) {
        zr[n] = sx[tid][2 * n];
        zi[n] = sx[tid][2 * n + 1];
    }
    fft32<-1>(zr, zi);

    const int tube = blockIdx.x * 128 + tid;
    const int b  = tube >> 16;
    const int ij = tube & 0xFFFF;

    __nv_bfloat16* const* dst4 = nullptr;  // silence unused warning path
    (void)dst4;

#pragma unroll
    for (int k = 0; k <= 32; ++k) {
        float Xr, Xi;
        if (k == 0 || k == 32) {
            const float e = zr[0], o = zi[0];
            Xr = (k == 0) ? (e + o) : (e - o);
            Xi = 0.0f;
        } else {
            const float Zkr = zr[BR5[k]],             Zki = zi[BR5[k]];
            const float Zcr = zr[BR5[(32 - k) & 31]], Zci = -zi[BR5[(32 - k) & 31]];
            const float Er = 0.5f * (Zkr + Zcr), Ei = 0.5f * (Zki + Zci);
            const float Dr = 0.5f * (Zkr - Zcr), Di = 0.5f * (Zki - Zci);
            const float Or = Di, Oi = -Dr;
            Xr = Er + W64R[k] * Or + W64I[k] * Oi;
            Xi = Ei + W64R[k] * Oi - W64I[k] * Or;
        }
        const float Xs = Xr + Xi;

        const size_t off = (((size_t)(b * NF + k)) << 16) + ij;
        const __nv_bfloat16 rh = __float2bfloat16(Xr);
        const __nv_bfloat16 ih = __float2bfloat16(Xi);
        const __nv_bfloat16 sh = __float2bfloat16(Xs);
        const __nv_bfloat16 rl = __float2bfloat16(Xr - __bfloat162float(rh));
        const __nv_bfloat16 il = __float2bfloat16(Xi - __bfloat162float(ih));
        const __nv_bfloat16 sl = __float2bfloat16(Xs - __bfloat162float(sh));

        if (sel == 0) {
            g_A[0][off] = rh; g_A[1][off] = rl;
            g_A[2][off] = ih; g_A[3][off] = il;
            g_A[4][off] = sh; g_A[5][off] = sl;
        } else {
            g_B[0][off] = rh; g_B[1][off] = rl;
            g_B[2][off] = ih; g_B[3][off] = il;
            g_B[4][off] = sh; g_B[5][off] = sl;
        }
    }
}

// ===========================================================================
// Gauss complex GEMM on wmma bf16, 3-term hi/lo split per product.
//   T1 = Ar*Br, T2 = Ai*Bi, T3 = As*Bs;  Cre = T1-T2, Cim = T3-T1-T2
// CTA: 128 m x 64 n, 512 threads (16 warps @ 32x16), K=256 in 16 chunks,
// 3-stage cp.async pipeline, one __syncthreads per chunk.
// ===========================================================================
#define CP_ASYNC16(dst, src) \
    asm volatile("cp.async.cg.shared.global [%0], [%1], 16;" :: "r"(dst), "l"(src) : "memory")
#define CP_COMMIT() asm volatile("cp.async.commit_group;" ::: "memory")
#define CP_WAIT1()  asm volatile("cp.async.wait_group 1;" ::: "memory")
#define CP_WAIT0()  asm volatile("cp.async.wait_group 0;" ::: "memory")

#define A_LDM 24
#define B_LDM 72
#define OF_B   (6 * 128 * A_LDM * 2)            // 36864 bytes: A block (6 arrays)
#define STG_BYTES (OF_B + 6 * 16 * B_LDM * 2)   // + B block 13824 = 50688
#define SMEM_GEMM (3 * STG_BYTES)               // 152064

__global__ __launch_bounds__(512) void cgemm_wmma_kernel()
{
    extern __shared__ char sm[];

    const int p  = blockIdx.z;
    const int m0 = blockIdx.x * 128;
    const int n0 = blockIdx.y * 64;
    const size_t pb = ((size_t)p) << 16;

    const int tid = threadIdx.x;
    const int wid = tid >> 5;
    const int wm  = wid & 3;        // 4 m-slots of 32 rows
    const int wn  = wid >> 2;       // 4 n-slots of 16 cols

    // cp.async mapping.
    // A block: 6 arrays x 128 rows x 16 k = 1536 16B-ops (2 per row)
    const int ao   = tid;                        // base op id; 3 waves of 512
    // B block: 6 arrays x 16 rows x 64 n = 768 16B-ops (8 per row)
    const uint32_t base = (uint32_t)__cvta_generic_to_shared(sm);

    wmma::fragment<wmma::accumulator, 16, 16, 16, float> t1[2], t2[2], t3[2];
#pragma unroll
    for (int fm = 0; fm < 2; ++fm) {
        wmma::fill_fragment(t1[fm], 0.0f);
        wmma::fill_fragment(t2[fm], 0.0f);
        wmma::fill_fragment(t3[fm], 0.0f);
    }

#define LOAD_CHUNK(st, c) do {                                                   \
        const int _k0 = (c) * 16;                                                \
        const uint32_t _sb = base + (uint32_t)(st) * STG_BYTES;                  \
        _Pragma("unroll")                                                        \
        for (int t = 0; t < 3; ++t) {                                            \
            const int o = ao + t * 512;            /* 0..1535 */                 \
            const int arr = o >> 8;                                              \
            const int rem = o & 255;                                             \
            const int row = rem >> 1;                                            \
            const int half = rem & 1;                                            \
            CP_ASYNC16(_sb + (uint32_t)(arr * 128 * A_LDM + row * A_LDM + half * 8) * 2, \
                       &g_A[arr][pb + (size_t)(m0 + row) * 256 + _k0 + half * 8]);       \
        }                                                                        \
        _Pragma("unroll")                                                        \
        for (int t = 0; t < 2; ++t) {                                            \
            const int o = ao + t * 512;                                          \
            if (o < 768) {                                                       \
                const int arr = o >> 7;                                          \
                const int rem = o & 127;                                         \
                const int row = rem >> 3;                                        \
                const int cb  = rem & 7;                                         \
                CP_ASYNC16(_sb + OF_B + (uint32_t)(arr * 16 * B_LDM + row * B_LDM + cb * 8) * 2, \
                           &g_B[arr][pb + (size_t)(_k0 + row) * 256 + n0 + cb * 8]);             \
            }                                                                    \
        }                                                                        \
        CP_COMMIT();                                                             \
    } while (0)

    LOAD_CHUNK(0, 0);
    LOAD_CHUNK(1, 1);

    for (int c = 0; c < 16; ++c) {
        const int st = c % 3;
        if (c == 15) { CP_WAIT0(); } else { CP_WAIT1(); }
        __syncthreads();

        const char* stg = sm + st * STG_BYTES;
        const __nv_bfloat16* Abase = reinterpret_cast<const __nv_bfloat16*>(stg);
        const __nv_bfloat16* Bbase = reinterpret_cast<const __nv_bfloat16*>(stg + OF_B);

        // B fragments (6) at col wn*16
        wmma::fragment<wmma::matrix_b, 16, 16, 16, __nv_bfloat16, wmma::row_major> fb[6];
#pragma unroll
        for (int a = 0; a < 6; ++a)
            wmma::load_matrix_sync(fb[a], Bbase + a * 16 * B_LDM + wn * 16, B_LDM);

#pragma unroll
        for (int fm = 0; fm < 2; ++fm) {
            const int mrow = wm * 32 + fm * 16;
            wmma::fragment<wmma::matrix_a, 16, 16, 16, __nv_bfloat16, wmma::row_major> fa[6];
#pragma unroll
            for (int a = 0; a < 6; ++a)
                wmma::load_matrix_sync(fa[a], Abase + a * 128 * A_LDM + mrow * A_LDM, A_LDM);

            // T1 = Ar*Br (hh + hl + lh)
            wmma::mma_sync(t1[fm], fa[0], fb[0], t1[fm]);
            wmma::mma_sync(t1[fm], fa[0], fb[1], t1[fm]);
            wmma::mma_sync(t1[fm], fa[1], fb[0], t1[fm]);
            // T2 = Ai*Bi
            wmma::mma_sync(t2[fm], fa[2], fb[2], t2[fm]);
            wmma::mma_sync(t2[fm], fa[2], fb[3], t2[fm]);
            wmma::mma_sync(t2[fm], fa[3], fb[2], t2[fm]);
            // T3 = As*Bs
            wmma::mma_sync(t3[fm], fa[4], fb[4], t3[fm]);
            wmma::mma_sync(t3[fm], fa[4], fb[5], t3[fm]);
            wmma::mma_sync(t3[fm], fa[5], fb[4], t3[fm]);
        }
        if (c + 2 < 16) LOAD_CHUNK((c + 2) % 3, c + 2);
    }

    // Epilogue: Cre = T1 - T2, Cim = T3 - T1 - T2 (elementwise on frags)
#pragma unroll
    for (int fm = 0; fm < 2; ++fm) {
        wmma::fragment<wmma::accumulator, 16, 16, 16, float> cre, cim;
#pragma unroll
        for (int e = 0; e < cre.num_elements; ++e) {
            const float v1 = t1[fm].x[e], v2 = t2[fm].x[e], v3 = t3[fm].x[e];
            cre.x[e] = v1 - v2;
            cim.x[e] = v3 - v1 - v2;
        }
        const size_t co = pb + (size_t)(m0 + wm * 32 + fm * 16) * 256 + n0 + wn * 16;
        wmma::store_matrix_sync(g_Cre + co, cre, 256, wmma::mem_row_major);
        wmma::store_matrix_sync(g_Cim + co, cim, 256, wmma::mem_row_major);
    }
}

// ===========================================================================
// Inverse: Hermitian spectrum (planar Cre/Cim) -> real 64 via iFFT32.
// ===========================================================================
__global__ __launch_bounds__(256) void ifft_kernel(float* __restrict__ out)
{
    const int tube = blockIdx.x * 256 + threadIdx.x;
    const int b    = tube >> 16;
    const int in_  = tube & 0xFFFF;

    float zr[32], zi[32];
    const float h = 1.0f / 64.0f;

    {
        const size_t o0  = (((size_t)(b * NF + 0))  << 16) + in_;
        const size_t o32 = (((size_t)(b * NF + 32)) << 16) + in_;
        const float X0r = g_Cre[o0],  X0i = g_Cim[o0];
        const float X2r = g_Cre[o32], X2i = g_Cim[o32];
        const float Er = (X0r + X2r) * h, Ei = (X0i + X2i) * h;
        const float Or = (X0r - X2r) * h, Oi = (X0i - X2i) * h;
        zr[0] = Er - Oi;
        zi[0] = Ei + Or;
    }
#pragma unroll
    for (int k = 1; k <= 16; ++k) {
        const size_t ok = (((size_t)(b * NF + k))        << 16) + in_;
        const size_t oq = (((size_t)(b * NF + (32 - k))) << 16) + in_;
        const float Xkr = g_Cre[ok], Xki = g_Cim[ok];
        const float Xqr = g_Cre[oq], Xqi = g_Cim[oq];
        const float Er = (Xkr + Xqr) * h, Ei = (Xki - Xqi) * h;
        const float Dr = (Xkr - Xqr) * h, Di = (Xki + Xqi) * h;
        const float Or = Dr * W64R[k] - Di * W64I[k];
        const float Oi = Dr * W64I[k] + Di * W64R[k];
        zr[k] = Er - Oi;
        zi[k] = Ei + Or;
        if (k < 16) {
            zr[32 - k] = Er + Oi;
            zi[32 - k] = Or - Ei;
        }
    }

    fft32<1>(zr, zi);

    float* dst = out + (size_t)tube * N3;
#pragma unroll
    for (int n = 0; n < 32; n += 2) {
        const int p0 = BR5[n], p1 = BR5[n + 1];
        *reinterpret_cast<float4*>(dst + 2 * n) =
            make_float4(zr[p0], zi[p0], zr[p1], zi[p1]);
    }
}

// ===========================================================================
extern "C" void kernel_launch(void* const* d_in, const int* in_sizes, int n_in,
                              void* d_out, int out_size)
{
    const float* A = (const float*)d_in[0];
    const float* B = (const float*)d_in[1];
    float* out = (float*)d_out;

    cudaFuncSetAttribute(cgemm_wmma_kernel,
                         cudaFuncAttributeMaxDynamicSharedMemorySize, SMEM_GEMM);

    const int fftBlocks = NTUBES / 128;          // 4096
    fft_fwd_kernel<<<fftBlocks, 128>>>(A, 0);
    fft_fwd_kernel<<<fftBlocks, 128>>>(B, 1);

    dim3 ggrid(2, 4, NFP);                       // (m, n, plane-slowest) 2112 CTAs
    cgemm_wmma_kernel<<<ggrid, 512, SMEM_GEMM>>>();

    ifft_kernel<<<NTUBES / 256, 256>>>(out);
}